// round 3
// baseline (speedup 1.0000x reference)
#include <cuda_runtime.h>
#include <cuda_bf16.h>
#include <cstdint>
#include <math.h>

#define N_ROWS 2048
#define DIM    512
#define K_NEG  65536
#define TEMP   0.2f
#define EPSV   1e-8f

#define BM 128
#define BN 128
#define BK 32
#define SAS 40            // smem row stride in bf16 (32 + 8 pad)
#define NBLKS (K_NEG / BN) // 512

// Scratch (static __device__ globals: allocation-free per harness rules)
__device__ __nv_bfloat16 g_qbf[N_ROWS * DIM];
__device__ __nv_bfloat16 g_ubf[(size_t)K_NEG * DIM];
__device__ float g_rowscale[N_ROWS];   // 1/(||q||*T)
__device__ float g_lpos[N_ROWS];
__device__ float g_colscale[K_NEG];    // 1/||u||
__device__ float g_part[N_ROWS * NBLKS];
__device__ float g_rowloss[N_ROWS];

// ---------------------------------------------------------------------------
// Kernel 1: query/keys norms, l_pos (fp32-exact), bf16 convert of query
// ---------------------------------------------------------------------------
__global__ void prep_qk(const float* __restrict__ q, const float* __restrict__ k) {
    int r = blockIdx.x;
    int tid = threadIdx.x;
    const float* qr = q + r * DIM;
    const float* kr = k + r * DIM;
    float sq = 0.f, sk = 0.f, dp = 0.f;
    for (int d = tid; d < DIM; d += blockDim.x) {
        float qv = qr[d], kv = kr[d];
        sq += qv * qv; sk += kv * kv; dp += qv * kv;
        g_qbf[r * DIM + d] = __float2bfloat16(qv);
    }
    #pragma unroll
    for (int o = 16; o; o >>= 1) {
        sq += __shfl_xor_sync(0xffffffffu, sq, o);
        sk += __shfl_xor_sync(0xffffffffu, sk, o);
        dp += __shfl_xor_sync(0xffffffffu, dp, o);
    }
    __shared__ float s1[8], s2[8], s3[8];
    int w = tid >> 5;
    if ((tid & 31) == 0) { s1[w] = sq; s2[w] = sk; s3[w] = dp; }
    __syncthreads();
    if (tid == 0) {
        float a = 0.f, b = 0.f, c = 0.f;
        for (int i = 0; i < 8; i++) { a += s1[i]; b += s2[i]; c += s3[i]; }
        float qn = sqrtf(a), kn = sqrtf(b);
        g_rowscale[r] = 1.f / (qn * TEMP);
        g_lpos[r] = c / fmaxf(qn * kn, EPSV) / TEMP;
    }
}

// ---------------------------------------------------------------------------
// Kernel 2: queue norms + bf16 convert
// ---------------------------------------------------------------------------
__global__ void prep_u(const float* __restrict__ u) {
    int r = blockIdx.x;
    int tid = threadIdx.x;
    const float* ur = u + (size_t)r * DIM;
    float su = 0.f;
    for (int d = tid; d < DIM; d += blockDim.x) {
        float uv = ur[d];
        su += uv * uv;
        g_ubf[(size_t)r * DIM + d] = __float2bfloat16(uv);
    }
    #pragma unroll
    for (int o = 16; o; o >>= 1) su += __shfl_xor_sync(0xffffffffu, su, o);
    __shared__ float s1[4];
    int w = tid >> 5;
    if ((tid & 31) == 0) s1[w] = su;
    __syncthreads();
    if (tid == 0) {
        float a = s1[0] + s1[1] + s1[2] + s1[3];
        g_colscale[r] = 1.f / sqrtf(a);
    }
}

// ---------------------------------------------------------------------------
// Kernel 3: fused GEMM + exp + per-tile row sum.
// Tile: BM=128 x BN=128, 256 threads (8 warps: 2 M x 4 N), warp tile 64x32.
// mma.sync.aligned.m16n8k16.row.col bf16->f32.
// ---------------------------------------------------------------------------
__global__ __launch_bounds__(256) void gemm_lse() {
    const int mblk = blockIdx.x;
    const int nblk = blockIdx.y;
    const int tid = threadIdx.x;
    const int lane = tid & 31;
    const int wid = tid >> 5;
    const int wm = wid >> 2;   // 0..1
    const int wn = wid & 3;    // 0..3

    __shared__ __align__(16) __nv_bfloat16 sA[2][BM * SAS];
    __shared__ __align__(16) __nv_bfloat16 sB[2][BN * SAS];
    __shared__ float s_rs[BM], s_cs[BN];
    __shared__ float sred[4][BM];

    if (tid < 128) {
        s_rs[tid] = g_rowscale[mblk * BM + tid];
        s_cs[tid] = g_colscale[nblk * BN + tid];
    }

    const uint32_t saA = (uint32_t)__cvta_generic_to_shared(&sA[0][0]);
    const uint32_t saB = (uint32_t)__cvta_generic_to_shared(&sB[0][0]);
    const uint32_t BUFB = BM * SAS * 2;  // bytes per stage buffer (same A/B)

    float acc[4][4][4];
    #pragma unroll
    for (int i = 0; i < 4; i++)
        #pragma unroll
        for (int j = 0; j < 4; j++)
            #pragma unroll
            for (int v = 0; v < 4; v++) acc[i][j][v] = 0.f;

    auto load_stage = [&](int ks, int buf) {
        const int kk = ks * BK;
        #pragma unroll
        for (int it = 0; it < 4; it++) {
            int c = tid + it * 256;          // 0..1023
            bool isA = (c < 512);
            int cc = isA ? c : (c - 512);
            int row = cc >> 2;               // 0..127
            int seg = cc & 3;                // 16B segment within 64B row chunk
            const __nv_bfloat16* gp = isA
                ? (g_qbf + (size_t)(mblk * BM + row) * DIM + kk + seg * 8)
                : (g_ubf + (size_t)(nblk * BN + row) * DIM + kk + seg * 8);
            uint32_t sp = (isA ? saA : saB) + (uint32_t)buf * BUFB
                        + (uint32_t)(row * SAS + seg * 8) * 2;
            asm volatile("cp.async.cg.shared.global [%0], [%1], 16;\n"
                         :: "r"(sp), "l"(gp));
        }
        asm volatile("cp.async.commit_group;\n");
    };

    load_stage(0, 0);

    const int NST = DIM / BK;  // 16
    for (int ks = 0; ks < NST; ks++) {
        const int buf = ks & 1;
        asm volatile("cp.async.wait_group 0;\n");
        __syncthreads();
        if (ks + 1 < NST) load_stage(ks + 1, buf ^ 1);

        #pragma unroll
        for (int kk2 = 0; kk2 < 2; kk2++) {
            uint32_t a[4][4], b[4][2];
            #pragma unroll
            for (int i = 0; i < 4; i++) {
                int row = wm * 64 + i * 16 + (lane & 15);
                int col = kk2 * 16 + (lane >> 4) * 8;
                uint32_t addr = saA + (uint32_t)buf * BUFB + (uint32_t)(row * SAS + col) * 2;
                asm volatile("ldmatrix.sync.aligned.m8n8.x4.shared.b16 {%0,%1,%2,%3}, [%4];\n"
                             : "=r"(a[i][0]), "=r"(a[i][1]), "=r"(a[i][2]), "=r"(a[i][3])
                             : "r"(addr));
            }
            #pragma unroll
            for (int j = 0; j < 4; j++) {
                int row = wn * 32 + j * 8 + (lane & 7);
                int col = kk2 * 16 + ((lane >> 3) & 1) * 8;
                uint32_t addr = saB + (uint32_t)buf * BUFB + (uint32_t)(row * SAS + col) * 2;
                asm volatile("ldmatrix.sync.aligned.m8n8.x2.shared.b16 {%0,%1}, [%2];\n"
                             : "=r"(b[j][0]), "=r"(b[j][1]) : "r"(addr));
            }
            #pragma unroll
            for (int i = 0; i < 4; i++)
                #pragma unroll
                for (int j = 0; j < 4; j++)
                    asm volatile(
                        "mma.sync.aligned.m16n8k16.row.col.f32.bf16.bf16.f32 "
                        "{%0,%1,%2,%3}, {%4,%5,%6,%7}, {%8,%9}, {%0,%1,%2,%3};\n"
                        : "+f"(acc[i][j][0]), "+f"(acc[i][j][1]),
                          "+f"(acc[i][j][2]), "+f"(acc[i][j][3])
                        : "r"(a[i][0]), "r"(a[i][1]), "r"(a[i][2]), "r"(a[i][3]),
                          "r"(b[j][0]), "r"(b[j][1]));
        }
    }

    // Epilogue: logits -> exp -> row sums over this 128-col tile.
    #pragma unroll
    for (int i = 0; i < 4; i++) {
        int r0 = wm * 64 + i * 16 + (lane >> 2);
        float rs0 = s_rs[r0], rs1 = s_rs[r0 + 8];
        float sum0 = 0.f, sum1 = 0.f;
        #pragma unroll
        for (int j = 0; j < 4; j++) {
            int c0 = wn * 32 + j * 8 + (lane & 3) * 2;
            float cs0 = s_cs[c0], cs1 = s_cs[c0 + 1];
            sum0 += __expf(acc[i][j][0] * rs0 * cs0) + __expf(acc[i][j][1] * rs0 * cs1);
            sum1 += __expf(acc[i][j][2] * rs1 * cs0) + __expf(acc[i][j][3] * rs1 * cs1);
        }
        sum0 += __shfl_xor_sync(0xffffffffu, sum0, 1);
        sum0 += __shfl_xor_sync(0xffffffffu, sum0, 2);
        sum1 += __shfl_xor_sync(0xffffffffu, sum1, 1);
        sum1 += __shfl_xor_sync(0xffffffffu, sum1, 2);
        if ((lane & 3) == 0) {
            sred[wn][r0] = sum0;
            sred[wn][r0 + 8] = sum1;
        }
    }
    __syncthreads();
    if (tid < 128) {
        float p = sred[0][tid] + sred[1][tid] + sred[2][tid] + sred[3][tid];
        g_part[(size_t)(mblk * BM + tid) * NBLKS + nblk] = p;
    }
}

// ---------------------------------------------------------------------------
// Kernel 4: per-row reduce of partials -> rowloss = lse - l_pos
// ---------------------------------------------------------------------------
__global__ void reduce_row() {
    int r = blockIdx.x;
    int tid = threadIdx.x;
    float s = 0.f;
    for (int i = tid; i < NBLKS; i += blockDim.x) s += g_part[(size_t)r * NBLKS + i];
    #pragma unroll
    for (int o = 16; o; o >>= 1) s += __shfl_xor_sync(0xffffffffu, s, o);
    __shared__ float sw[8];
    int w = tid >> 5;
    if ((tid & 31) == 0) sw[w] = s;
    __syncthreads();
    if (tid == 0) {
        float tot = 0.f;
        for (int i = 0; i < 8; i++) tot += sw[i];
        float lp = g_lpos[r];
        tot += expf(lp);                 // positive logit term
        g_rowloss[r] = logf(tot) - lp;   // lse - l_pos (no max needed: |logit|<=5)
    }
}

// ---------------------------------------------------------------------------
// Kernel 5: mean over rows -> output scalar
// ---------------------------------------------------------------------------
__global__ void finalize(float* __restrict__ out) {
    int tid = threadIdx.x;
    float s = 0.f;
    for (int i = tid; i < N_ROWS; i += blockDim.x) s += g_rowloss[i];
    #pragma unroll
    for (int o = 16; o; o >>= 1) s += __shfl_xor_sync(0xffffffffu, s, o);
    __shared__ float sw[32];
    int w = tid >> 5;
    if ((tid & 31) == 0) sw[w] = s;
    __syncthreads();
    if (tid == 0) {
        float tot = 0.f;
        int nw = blockDim.x >> 5;
        for (int i = 0; i < nw; i++) tot += sw[i];
        out[0] = tot / (float)N_ROWS;
    }
}

// ---------------------------------------------------------------------------
extern "C" void kernel_launch(void* const* d_in, const int* in_sizes, int n_in,
                              void* d_out, int out_size) {
    const float* query = (const float*)d_in[0];
    const float* keys  = (const float*)d_in[1];
    const float* queue = (const float*)d_in[2];
    float* out = (float*)d_out;

    prep_qk<<<N_ROWS, 256>>>(query, keys);
    prep_u<<<K_NEG, 128>>>(queue);
    dim3 grid(N_ROWS / BM, NBLKS);   // (16, 512): x-major keeps B-tile sharers adjacent
    gemm_lse<<<grid, 256>>>();
    reduce_row<<<N_ROWS, 256>>>();
    finalize<<<1, 1024>>>(out);
}

// round 5
// speedup vs baseline: 1.2250x; 1.2250x over previous
#include <cuda_runtime.h>
#include <cuda_bf16.h>
#include <cstdint>
#include <math.h>

#define N_ROWS 2048
#define DIM    512
#define K_NEG  65536
#define TEMP   0.2f
#define EPSV   1e-8f
#define LOG2E  1.4426950408889634f

// GEMM tiling
#define BM 128
#define BN 128
#define KC 128                 // K per pipeline chunk (fp8 bytes)
#define NCHT 4                 // chunks per tile (DIM/KC)
#define NNB (K_NEG / BN)       // 512 n-blocks
#define YCTAS 9                // 16*9 = 144 CTAs = 1 wave
#define NPART (YCTAS * 4)      // 36 partials per row (one per (y, wn))

// SMEM layout (conflict-free pad strides)
#define ASTR 528u              // bytes per A row (512 + 16): 132 words, 132g%32=4g
#define BSTR 144u              // bytes per B row (128 + 16): 36 words,  36g%32=4g
#define A_BYTES   (128u * ASTR)          // 67584
#define B_STAGE   (128u * BSTR)          // 18432
#define OFF_A     0u
#define OFF_B     A_BYTES
#define OFF_CS    (OFF_B + 4u * B_STAGE) // 141312 (2 x 512B cs buffers)
#define SMEM_TOTAL (OFF_CS + 1024u)      // 142336

// Scratch
__device__ uint8_t g_qf8[N_ROWS * DIM];
__device__ uint8_t g_uf8[(size_t)K_NEG * DIM];
__device__ float g_rowscale[N_ROWS];   // log2e / (||q||*T)
__device__ float g_lpos[N_ROWS];
__device__ float g_colscale[K_NEG];    // 1/||u||
__device__ float g_part[N_ROWS * NPART];
__device__ float g_rowloss[N_ROWS];

// ---------------- helpers ----------------
__device__ __forceinline__ uint32_t smem_u32(const void* p) {
    uint32_t a;
    asm("{ .reg .u64 t; cvta.to.shared.u64 t, %1; cvt.u32.u64 %0, t; }" : "=r"(a) : "l"(p));
    return a;
}
__device__ __forceinline__ void cp16(uint32_t sp, const void* gp) {
    asm volatile("cp.async.cg.shared.global [%0], [%1], 16;\n" :: "r"(sp), "l"(gp));
}
__device__ __forceinline__ uint32_t lds32(uint32_t a) {
    uint32_t v;
    asm volatile("ld.shared.b32 %0, [%1];" : "=r"(v) : "r"(a));
    return v;
}
__device__ __forceinline__ float ex2f(float x) {
    float r;
    asm("ex2.approx.ftz.f32 %0, %1;" : "=f"(r) : "f"(x));
    return r;
}
// pack 2 fp32 -> e4m3x2 (first src -> high byte)
__device__ __forceinline__ uint16_t f2e4m3x2(float hi, float lo) {
    uint16_t r;
    asm("cvt.rn.satfinite.e4m3x2.f32 %0, %1, %2;" : "=h"(r) : "f"(hi), "f"(lo));
    return r;
}
__device__ __forceinline__ void mma_fp8(float* c, const uint32_t* a, const uint32_t* b) {
    asm volatile(
        "mma.sync.aligned.m16n8k32.row.col.f32.e4m3.e4m3.f32 "
        "{%0,%1,%2,%3}, {%4,%5,%6,%7}, {%8,%9}, {%0,%1,%2,%3};\n"
        : "+f"(c[0]), "+f"(c[1]), "+f"(c[2]), "+f"(c[3])
        : "r"(a[0]), "r"(a[1]), "r"(a[2]), "r"(a[3]), "r"(b[0]), "r"(b[1]));
}

// ---------------------------------------------------------------------------
// Kernel 1: query/keys norms, l_pos (fp32-exact), fp8 convert of query
// ---------------------------------------------------------------------------
__global__ void prep_qk(const float* __restrict__ q, const float* __restrict__ k) {
    int r = blockIdx.x;
    int tid = threadIdx.x;   // 256
    const float* qr = q + r * DIM;
    const float* kr = k + r * DIM;
    float sq = 0.f, sk = 0.f, dp = 0.f;
    {   // 2 elems per thread
        int d = tid * 2;
        float q0 = qr[d], q1 = qr[d + 1];
        float k0 = kr[d], k1 = kr[d + 1];
        sq = q0 * q0 + q1 * q1;
        sk = k0 * k0 + k1 * k1;
        dp = q0 * k0 + q1 * k1;
        ((uint16_t*)g_qf8)[(r * DIM + d) >> 1] = f2e4m3x2(q1, q0);
    }
    #pragma unroll
    for (int o = 16; o; o >>= 1) {
        sq += __shfl_xor_sync(0xffffffffu, sq, o);
        sk += __shfl_xor_sync(0xffffffffu, sk, o);
        dp += __shfl_xor_sync(0xffffffffu, dp, o);
    }
    __shared__ float s1[8], s2[8], s3[8];
    int w = tid >> 5;
    if ((tid & 31) == 0) { s1[w] = sq; s2[w] = sk; s3[w] = dp; }
    __syncthreads();
    if (tid == 0) {
        float a = 0.f, b = 0.f, c = 0.f;
        for (int i = 0; i < 8; i++) { a += s1[i]; b += s2[i]; c += s3[i]; }
        float qn = sqrtf(a), kn = sqrtf(b);
        g_rowscale[r] = LOG2E / (qn * TEMP);
        g_lpos[r] = c / fmaxf(qn * kn, EPSV) / TEMP;
    }
}

// ---------------------------------------------------------------------------
// Kernel 2: queue norms + fp8 convert (float4 reads, uint32 fp8 writes)
// ---------------------------------------------------------------------------
__global__ void prep_u(const float* __restrict__ u) {
    int r = blockIdx.x;
    int tid = threadIdx.x;   // 128
    const float4* ur = (const float4*)(u + (size_t)r * DIM);
    float4 v = ur[tid];
    float su = v.x * v.x + v.y * v.y + v.z * v.z + v.w * v.w;
    uint32_t lo = f2e4m3x2(v.y, v.x);
    uint32_t hi = f2e4m3x2(v.w, v.z);
    ((uint32_t*)g_uf8)[((size_t)r * DIM >> 2) + tid] = (hi << 16) | lo;
    #pragma unroll
    for (int o = 16; o; o >>= 1) su += __shfl_xor_sync(0xffffffffu, su, o);
    __shared__ float s1[4];
    int w = tid >> 5;
    if ((tid & 31) == 0) s1[w] = su;
    __syncthreads();
    if (tid == 0) g_colscale[r] = rsqrtf(s1[0] + s1[1] + s1[2] + s1[3]);
}

// ---------------------------------------------------------------------------
// Kernel 3: persistent fp8 mma.sync GEMM + fused exp2/row-sum epilogue.
// Grid (16, 9). CTA (mb, y): A[mb] resident in SMEM; streams n-blocks
// y, y+9, ... with a 4-deep cp.async chunk ring (stage == chunk index).
// Warps: 2(m) x 4(n), warp tile 64x32, mma m16n8k32 e4m3.
// ---------------------------------------------------------------------------
__global__ void __launch_bounds__(256) gemm_lse() {
    extern __shared__ __align__(128) char smem[];
    const uint32_t sb = smem_u32(smem);
    const int tid = threadIdx.x;
    const int lane = tid & 31;
    const int wid = tid >> 5;
    const int wm = wid >> 2;       // 0..1
    const int wn = wid & 3;        // 0..3
    const int g = lane >> 2;       // 0..7
    const int t = lane & 3;        // 0..3
    const int mb = blockIdx.x;
    const int y = blockIdx.y;

    // Resident A: 128 rows x 512B, pad stride 528
    {
        const uint8_t* gA = g_qf8 + (size_t)mb * BM * DIM;
        #pragma unroll
        for (int i = 0; i < 16; i++) {
            int s = tid + i * 256;
            int r = s >> 5, s8 = s & 31;
            cp16(sb + OFF_A + r * ASTR + s8 * 16, gA + (size_t)r * DIM + s8 * 16);
        }
        asm volatile("cp.async.commit_group;\n");
    }

    // Per-thread row scales (8 rows: 4 m-tiles x 2 halves), log2e/T folded in
    float rs[8];
    #pragma unroll
    for (int i = 0; i < 4; i++)
        #pragma unroll
        for (int h = 0; h < 2; h++)
            rs[i * 2 + h] = g_rowscale[mb * BM + wm * 64 + i * 16 + h * 8 + g];

    // Per-thread A row byte offsets & B n bases
    uint32_t arow[8];
    #pragma unroll
    for (int i = 0; i < 4; i++)
        #pragma unroll
        for (int h = 0; h < 2; h++)
            arow[i * 2 + h] = sb + OFF_A + (wm * 64 + i * 16 + h * 8 + g) * ASTR + 4 * t;
    uint32_t bbase[4];
    #pragma unroll
    for (int j = 0; j < 4; j++)
        bbase[j] = sb + OFF_B + (wn * 32 + j * 8 + g) * BSTR + 4 * t;

    const int ntiles = (NNB - 1 - y) / YCTAS + 1;   // 56 or 57
    const int total = ntiles * NCHT;

    // chunk issue: stream s -> tile s>>2, chunk s&3, stage s&3
    auto issue = [&](int s) {
        if (s >= total) return;
        int tt = s >> 2, c = s & 3;
        int nb = y + tt * YCTAS;
        if (c == 0 && tid < 32) {  // colscale for this tile (ping-pong by tile parity)
            cp16(sb + OFF_CS + (uint32_t)(tt & 1) * 512 + tid * 16,
                 g_colscale + nb * BN + tid * 4);
        }
        const uint8_t* gB = g_uf8 + (size_t)nb * BN * DIM + c * KC;
        uint32_t bb = sb + OFF_B + (uint32_t)c * B_STAGE;
        #pragma unroll
        for (int i = 0; i < 4; i++) {
            int ss = tid + i * 256;
            int r = ss >> 3, s8 = ss & 7;
            cp16(bb + r * BSTR + s8 * 16, gB + (size_t)r * DIM + s8 * 16);
        }
        asm volatile("cp.async.commit_group;\n");
    };

    issue(0); issue(1); issue(2);

    float acc[4][4][4];
    #pragma unroll
    for (int i = 0; i < 4; i++)
        #pragma unroll
        for (int j = 0; j < 4; j++)
            #pragma unroll
            for (int v = 0; v < 4; v++) acc[i][j][v] = 0.f;
    float rsum[8];
    #pragma unroll
    for (int i = 0; i < 8; i++) rsum[i] = 0.f;

    #pragma unroll 1
    for (int s = 0; s < total; s++) {
        const int c = s & 3;
        asm volatile("cp.async.wait_group 2;\n");
        __syncthreads();
        issue(s + 3);

        // consume chunk c (stage c): 4 k32 steps
        const uint32_t acol = (uint32_t)(c * KC);
        const uint32_t bstg = (uint32_t)c * B_STAGE;
        #pragma unroll
        for (int st = 0; st < 4; st++) {
            const uint32_t ka = acol + st * 32;
            const uint32_t kb = bstg + st * 32;
            uint32_t b[4][2];
            #pragma unroll
            for (int j = 0; j < 4; j++) {
                b[j][0] = lds32(bbase[j] + kb);
                b[j][1] = lds32(bbase[j] + kb + 16);
            }
            #pragma unroll
            for (int i = 0; i < 4; i++) {
                uint32_t a[4];
                a[0] = lds32(arow[i * 2 + 0] + ka);
                a[1] = lds32(arow[i * 2 + 1] + ka);
                a[2] = lds32(arow[i * 2 + 0] + ka + 16);
                a[3] = lds32(arow[i * 2 + 1] + ka + 16);
                #pragma unroll
                for (int j = 0; j < 4; j++) mma_fp8(acc[i][j], a, b[j]);
            }
        }

        if (c == 3) {   // tile complete: exp2 + accumulate row sums, reset accs
            const uint32_t csb = sb + OFF_CS + (uint32_t)((s >> 2) & 1) * 512;
            #pragma unroll
            for (int j = 0; j < 4; j++) {
                float2 cs;
                asm volatile("ld.shared.v2.f32 {%0,%1}, [%2];"
                             : "=f"(cs.x), "=f"(cs.y)
                             : "r"(csb + (uint32_t)(wn * 32 + j * 8 + 2 * t) * 4));
                #pragma unroll
                for (int i = 0; i < 4; i++) {
                    float r0 = rs[i * 2 + 0], r1 = rs[i * 2 + 1];
                    rsum[i * 2 + 0] += ex2f(acc[i][j][0] * r0 * cs.x)
                                     + ex2f(acc[i][j][1] * r0 * cs.y);
                    rsum[i * 2 + 1] += ex2f(acc[i][j][2] * r1 * cs.x)
                                     + ex2f(acc[i][j][3] * r1 * cs.y);
                    acc[i][j][0] = 0.f; acc[i][j][1] = 0.f;
                    acc[i][j][2] = 0.f; acc[i][j][3] = 0.f;
                }
            }
        }
    }

    // reduce over quad (t) and write one partial per (row, y, wn)
    #pragma unroll
    for (int i = 0; i < 8; i++) {
        rsum[i] += __shfl_xor_sync(0xffffffffu, rsum[i], 1);
        rsum[i] += __shfl_xor_sync(0xffffffffu, rsum[i], 2);
    }
    if (t == 0) {
        #pragma unroll
        for (int i = 0; i < 4; i++)
            #pragma unroll
            for (int h = 0; h < 2; h++) {
                int row = mb * BM + wm * 64 + i * 16 + h * 8 + g;
                g_part[(size_t)row * NPART + y * 4 + wn] = rsum[i * 2 + h];
            }
    }
}

// ---------------------------------------------------------------------------
// Kernel 4: per-row reduce of 36 partials -> rowloss = lse - l_pos
// ---------------------------------------------------------------------------
__global__ void reduce_row() {
    int r = blockIdx.x;
    int tid = threadIdx.x;   // 32
    float s = 0.f;
    for (int i = tid; i < NPART; i += 32) s += g_part[(size_t)r * NPART + i];
    #pragma unroll
    for (int o = 16; o; o >>= 1) s += __shfl_xor_sync(0xffffffffu, s, o);
    if (tid == 0) {
        float lp = g_lpos[r];
        s += expf(lp);                 // positive logit term
        g_rowloss[r] = logf(s) - lp;   // |logit|<=~6 -> no max subtraction needed
    }
}

// ---------------------------------------------------------------------------
// Kernel 5: mean over rows -> output scalar
// ---------------------------------------------------------------------------
__global__ void finalize(float* __restrict__ out) {
    int tid = threadIdx.x;
    float s = 0.f;
    for (int i = tid; i < N_ROWS; i += blockDim.x) s += g_rowloss[i];
    #pragma unroll
    for (int o = 16; o; o >>= 1) s += __shfl_xor_sync(0xffffffffu, s, o);
    __shared__ float sw[32];
    int w = tid >> 5;
    if ((tid & 31) == 0) sw[w] = s;
    __syncthreads();
    if (tid == 0) {
        float tot = 0.f;
        int nw = blockDim.x >> 5;
        for (int i = 0; i < nw; i++) tot += sw[i];
        out[0] = tot / (float)N_ROWS;
    }
}

// ---------------------------------------------------------------------------
extern "C" void kernel_launch(void* const* d_in, const int* in_sizes, int n_in,
                              void* d_out, int out_size) {
    const float* query = (const float*)d_in[0];
    const float* keys  = (const float*)d_in[1];
    const float* queue = (const float*)d_in[2];
    float* out = (float*)d_out;

    cudaFuncSetAttribute(gemm_lse, cudaFuncAttributeMaxDynamicSharedMemorySize, SMEM_TOTAL);

    prep_qk<<<N_ROWS, 256>>>(query, keys);
    prep_u<<<K_NEG, 128>>>(queue);
    gemm_lse<<<dim3(N_ROWS / BM, YCTAS), 256, SMEM_TOTAL>>>();
    reduce_row<<<N_ROWS, 32>>>();
    finalize<<<1, 1024>>>(out);
}